// round 1
// baseline (speedup 1.0000x reference)
#include <cuda_runtime.h>
#include <cmath>

// Problem constants
#define BATCH   2
#define SEQ     2048
#define DIM     1024
#define NH      16
#define DKH     16      // head dim for q/k
#define DVH     64      // head dim for v
#define NTOK    (BATCH*SEQ)          // 4096
#define QCOLS   (NH*DKH)             // 256
#define KVCOLS  (NH*(DKH+DVH))       // 1280
#define OCOLS   (NH*DVH)             // 1024

// ---------------- scratch (static device memory; no allocs) ----------------
__device__ float g_projq [NTOK * QCOLS];          //  4 MB
__device__ float g_projkv[NTOK * KVCOLS];         // 20 MB
__device__ float g_qn[BATCH*NH*SEQ*DKH];          //  4 MB
__device__ float g_kn[BATCH*NH*SEQ*DKH];          //  4 MB
__device__ float g_vn[BATCH*NH*SEQ*DVH];          // 16 MB
__device__ float g_ao[NTOK * OCOLS];              // 16 MB

// ---------------- generic fp32 SGEMM: C[MxN] = A[MxK] @ B[KxN], row-major --
// Tile 64x64, BK=16, 256 threads, 4x4 per thread.
__global__ __launch_bounds__(256) void sgemm_kernel(
    const float* __restrict__ A, const float* __restrict__ Bm,
    float* __restrict__ C, int M, int Nc, int K)
{
    __shared__ float As[16][64];      // As[k][m] (transposed)
    __shared__ float Bs[16][64];      // Bs[k][n]

    const int t  = threadIdx.x;
    const int m0 = blockIdx.y * 64;
    const int n0 = blockIdx.x * 64;
    const int tx = t & 15;            // n-group
    const int ty = t >> 4;            // m-group

    float acc[4][4] = {};

    for (int k0 = 0; k0 < K; k0 += 16) {
        // load A tile (64 rows x 16 k), store transposed
        {
            const int r  = t >> 2;
            const int kq = (t & 3) * 4;
            float4 a = *(const float4*)&A[(size_t)(m0 + r) * K + k0 + kq];
            As[kq+0][r] = a.x; As[kq+1][r] = a.y;
            As[kq+2][r] = a.z; As[kq+3][r] = a.w;
        }
        // load B tile (16 k x 64 n)
        {
            const int r = t >> 4;
            const int c = (t & 15) * 4;
            *(float4*)&Bs[r][c] = *(const float4*)&Bm[(size_t)(k0 + r) * Nc + n0 + c];
        }
        __syncthreads();

        #pragma unroll
        for (int k = 0; k < 16; k++) {
            float4 a4 = *(float4*)&As[k][ty*4];
            float4 b4 = *(float4*)&Bs[k][tx*4];
            float av[4] = {a4.x, a4.y, a4.z, a4.w};
            float bv[4] = {b4.x, b4.y, b4.z, b4.w};
            #pragma unroll
            for (int i = 0; i < 4; i++)
                #pragma unroll
                for (int j = 0; j < 4; j++)
                    acc[i][j] += av[i] * bv[j];
        }
        __syncthreads();
    }

    #pragma unroll
    for (int i = 0; i < 4; i++) {
        float4 o = make_float4(acc[i][0], acc[i][1], acc[i][2], acc[i][3]);
        *(float4*)&C[(size_t)(m0 + ty*4 + i) * Nc + n0 + tx*4] = o;
    }
}

// ---------------- normalize + head-scatter ----------------
// One thread per (token, head): l2norm q (16), k (16), v (64); write head-major.
__global__ __launch_bounds__(256) void qkv_norm_kernel(
    const float* __restrict__ projq, const float* __restrict__ projkv,
    float* __restrict__ gq, float* __restrict__ gk, float* __restrict__ gv)
{
    int idx = blockIdx.x * blockDim.x + threadIdx.x;   // = tok*NH + h
    if (idx >= NTOK * NH) return;
    const int h   = idx & (NH - 1);
    const int tok = idx >> 4;
    const int b   = tok / SEQ;
    const int n   = tok - b * SEQ;
    const size_t bh = (size_t)(b * NH + h);

    // ---- q ----
    {
        const float* src = projq + (size_t)tok * QCOLS + h * DKH;
        float v[16];
        #pragma unroll
        for (int i = 0; i < 4; i++) {
            float4 x = *(const float4*)&src[i*4];
            v[i*4+0]=x.x; v[i*4+1]=x.y; v[i*4+2]=x.z; v[i*4+3]=x.w;
        }
        float ss = 0.f;
        #pragma unroll
        for (int i = 0; i < 16; i++) ss += v[i]*v[i];
        float sc = 1.f / fmaxf(sqrtf(ss), 1e-12f);
        float* dst = gq + ((bh * SEQ) + n) * DKH;
        #pragma unroll
        for (int i = 0; i < 4; i++) {
            float4 x = make_float4(v[i*4]*sc, v[i*4+1]*sc, v[i*4+2]*sc, v[i*4+3]*sc);
            *(float4*)&dst[i*4] = x;
        }
    }
    // ---- k ----
    {
        const float* src = projkv + (size_t)tok * KVCOLS + h * (DKH + DVH);
        float v[16];
        #pragma unroll
        for (int i = 0; i < 4; i++) {
            float4 x = *(const float4*)&src[i*4];
            v[i*4+0]=x.x; v[i*4+1]=x.y; v[i*4+2]=x.z; v[i*4+3]=x.w;
        }
        float ss = 0.f;
        #pragma unroll
        for (int i = 0; i < 16; i++) ss += v[i]*v[i];
        float sc = 1.f / fmaxf(sqrtf(ss), 1e-12f);
        float* dst = gk + ((bh * SEQ) + n) * DKH;
        #pragma unroll
        for (int i = 0; i < 4; i++) {
            float4 x = make_float4(v[i*4]*sc, v[i*4+1]*sc, v[i*4+2]*sc, v[i*4+3]*sc);
            *(float4*)&dst[i*4] = x;
        }
    }
    // ---- v ----
    {
        const float* src = projkv + (size_t)tok * KVCOLS + h * (DKH + DVH) + DKH;
        float v[64];
        #pragma unroll
        for (int i = 0; i < 16; i++) {
            float4 x = *(const float4*)&src[i*4];
            v[i*4+0]=x.x; v[i*4+1]=x.y; v[i*4+2]=x.z; v[i*4+3]=x.w;
        }
        float ss = 0.f;
        #pragma unroll
        for (int i = 0; i < 64; i++) ss += v[i]*v[i];
        float sc = 1.f / fmaxf(sqrtf(ss), 1e-12f);
        float* dst = gv + ((bh * SEQ) + n) * DVH;
        #pragma unroll
        for (int i = 0; i < 16; i++) {
            float4 x = make_float4(v[i*4]*sc, v[i*4+1]*sc, v[i*4+2]*sc, v[i*4+3]*sc);
            *(float4*)&dst[i*4] = x;
        }
    }
}

// ---------------- fused attention ----------------
// grid (SEQ/64, BATCH*NH), 256 threads. Per block: 64 queries x full key loop.
// S tile kept transposed in smem so the PV stage is all-broadcast float4 reads.
__global__ __launch_bounds__(256) void attn_kernel(
    const float* __restrict__ gq, const float* __restrict__ gk,
    const float* __restrict__ gv, float* __restrict__ gao)
{
    __shared__ float Qt[16][64];       // Qt[k][query]
    __shared__ float Kt[16][64];       // Kt[k][key]
    __shared__ float Vs[64][64];       // Vs[key][dv]
    __shared__ float St[64][68];       // St[key][query]; later reused as Os[query][dv]
    __shared__ float rscale[64];

    const int t  = threadIdx.x;
    const int bh = blockIdx.y;
    const int q0 = blockIdx.x * 64;
    const int tx = t & 15;             // query group (PV/QK) / dv group mapping below
    const int ty = t >> 4;

    const float* qb = gq + (size_t)bh * SEQ * DKH;
    const float* kb = gk + (size_t)bh * SEQ * DKH;
    const float* vb = gv + (size_t)bh * SEQ * DVH;

    // load Q tile once (64 x 16), transposed
    {
        const int r  = t >> 2;
        const int kq = (t & 3) * 4;
        float4 a = *(const float4*)&qb[(size_t)(q0 + r) * DKH + kq];
        Qt[kq+0][r] = a.x; Qt[kq+1][r] = a.y;
        Qt[kq+2][r] = a.z; Qt[kq+3][r] = a.w;
    }

    float acc[4][4] = {};   // acc[query i][dv j]; query = tx*4+i, dv = ty*4+j

    for (int k0 = 0; k0 < SEQ; k0 += 64) {
        // load K tile (64 keys x 16), transposed
        {
            const int r  = t >> 2;
            const int kq = (t & 3) * 4;
            float4 a = *(const float4*)&kb[(size_t)(k0 + r) * DKH + kq];
            Kt[kq+0][r] = a.x; Kt[kq+1][r] = a.y;
            Kt[kq+2][r] = a.z; Kt[kq+3][r] = a.w;
        }
        // load V tile (64 keys x 64 dv)
        #pragma unroll
        for (int ii = 0; ii < 4; ii++) {
            const int r = ii * 16 + (t >> 4);
            const int c = (t & 15) * 4;
            *(float4*)&Vs[r][c] = *(const float4*)&vb[(size_t)(k0 + r) * DVH + c];
        }
        __syncthreads();

        // S = Q @ K^T : this thread covers queries tx*4.., keys ty*4..
        float s[4][4] = {};
        #pragma unroll
        for (int k = 0; k < 16; k++) {
            float4 a4 = *(float4*)&Qt[k][tx*4];
            float4 b4 = *(float4*)&Kt[k][ty*4];
            float qv[4] = {a4.x, a4.y, a4.z, a4.w};
            float kv[4] = {b4.x, b4.y, b4.z, b4.w};
            #pragma unroll
            for (int i = 0; i < 4; i++)
                #pragma unroll
                for (int j = 0; j < 4; j++)
                    s[i][j] += qv[i] * kv[j];
        }
        // relu^2, store transposed: St[key][query]
        #pragma unroll
        for (int j = 0; j < 4; j++)
            #pragma unroll
            for (int i = 0; i < 4; i++) {
                float x = s[i][j];
                x = (x > 0.f) ? x * x : 0.f;
                St[ty*4 + j][tx*4 + i] = x;
            }
        __syncthreads();

        // acc += S @ V
        #pragma unroll
        for (int kk = 0; kk < 64; kk++) {
            float4 a4 = *(float4*)&St[kk][tx*4];
            float4 b4 = *(float4*)&Vs[kk][ty*4];
            float av[4] = {a4.x, a4.y, a4.z, a4.w};
            float bv[4] = {b4.x, b4.y, b4.z, b4.w};
            #pragma unroll
            for (int i = 0; i < 4; i++)
                #pragma unroll
                for (int j = 0; j < 4; j++)
                    acc[i][j] += av[i] * bv[j];
        }
        __syncthreads();
    }

    // epilogue: dump acc into St reused as Os[query][dv]
    #pragma unroll
    for (int i = 0; i < 4; i++)
        #pragma unroll
        for (int j = 0; j < 4; j++)
            St[tx*4 + i][ty*4 + j] = acc[i][j];
    __syncthreads();

    if (t < 64) {
        float ss = 0.f;
        #pragma unroll 8
        for (int j = 0; j < 64; j++) { float x = St[t][j]; ss += x * x; }
        float nrm = sqrtf(ss);
        rscale[t] = tanhf(nrm) / fmaxf(nrm, 1e-12f);
    }
    __syncthreads();

    // write tanh-normed rows to g_ao laid out (b, n, h*DVH)
    {
        const int b = bh >> 4;
        const int h = bh & 15;
        const int r = t >> 2;                    // query row 0..63
        const int cbase = (t & 3) * 16;
        const float sc = rscale[r];
        float* dst = gao + ((size_t)(b * SEQ + q0 + r)) * OCOLS + h * DVH + cbase;
        #pragma unroll
        for (int c = 0; c < 16; c += 4) {
            float4 v4 = *(float4*)&St[r][cbase + c];
            v4.x *= sc; v4.y *= sc; v4.z *= sc; v4.w *= sc;
            *(float4*)&dst[c] = v4;
        }
    }
}

// ---------------- host launch ----------------
extern "C" void kernel_launch(void* const* d_in, const int* in_sizes, int n_in,
                              void* d_out, int out_size)
{
    // resolve inputs by size (defensive against ordering)
    const float *tokens = nullptr, *Wq = nullptr, *Wkv = nullptr, *Wout = nullptr;
    for (int i = 0; i < n_in; i++) {
        switch (in_sizes[i]) {
            case NTOK * DIM:      tokens = (const float*)d_in[i]; break;  // 4194304
            case DIM * QCOLS:     Wq     = (const float*)d_in[i]; break;  // 262144
            case DIM * KVCOLS:    Wkv    = (const float*)d_in[i]; break;  // 1310720
            case OCOLS * DIM:     Wout   = (const float*)d_in[i]; break;  // 1048576
        }
    }
    // tokens and Wout share no size collisions with others; but tokens(4194304)
    // is unique, Wout(1048576) unique, ok.

    float *projq, *projkv, *qn, *kn, *vn, *ao;
    cudaGetSymbolAddress((void**)&projq,  g_projq);
    cudaGetSymbolAddress((void**)&projkv, g_projkv);
    cudaGetSymbolAddress((void**)&qn,     g_qn);
    cudaGetSymbolAddress((void**)&kn,     g_kn);
    cudaGetSymbolAddress((void**)&vn,     g_vn);
    cudaGetSymbolAddress((void**)&ao,     g_ao);

    // 1) projections
    sgemm_kernel<<<dim3(QCOLS/64,  NTOK/64), 256>>>(tokens, Wq,  projq,  NTOK, QCOLS,  DIM);
    sgemm_kernel<<<dim3(KVCOLS/64, NTOK/64), 256>>>(tokens, Wkv, projkv, NTOK, KVCOLS, DIM);

    // 2) normalize + head scatter
    qkv_norm_kernel<<<(NTOK*NH + 255)/256, 256>>>(projq, projkv, qn, kn, vn);

    // 3) fused relu^2 attention + tanh-norm
    attn_kernel<<<dim3(SEQ/64, BATCH*NH), 256>>>(qn, kn, vn, ao);

    // 4) output projection
    sgemm_kernel<<<dim3(DIM/64, NTOK/64), 256>>>(ao, Wout, (float*)d_out, NTOK, DIM, OCOLS);
}

// round 2
// speedup vs baseline: 2.4534x; 2.4534x over previous
#include <cuda_runtime.h>
#include <cmath>

// Problem constants
#define BATCH   2
#define SEQ     2048
#define DIM     1024
#define NH      16
#define DKH     16
#define DVH     64
#define NTOK    (BATCH*SEQ)          // 4096
#define QCOLS   (NH*DKH)             // 256
#define KVCOLS  (NH*(DKH+DVH))       // 1280
#define OCOLS   (NH*DVH)             // 1024

// ---------------- scratch ----------------
__device__ float g_projq [NTOK * QCOLS];
__device__ float g_projkv[NTOK * KVCOLS];
__device__ float g_qn[BATCH*NH*SEQ*DKH];
__device__ float g_kn[BATCH*NH*SEQ*DKH];
__device__ float g_vn[BATCH*NH*SEQ*DVH];
__device__ float g_ao[NTOK * OCOLS];

// ---------------- tf32 helpers ----------------
__device__ __forceinline__ unsigned f2tf(float x){
    unsigned r; asm("cvt.rna.tf32.f32 %0, %1;" : "=r"(r) : "f"(x)); return r;
}
__device__ __forceinline__ float f2tf_f(float x){ return __uint_as_float(f2tf(x)); }

// D += A(16x8) * B(8x8), tf32 in, fp32 accum.  row.col fragment layout.
__device__ __forceinline__ void mma8(float* c, const unsigned* a, const unsigned* b){
    asm volatile("mma.sync.aligned.m16n8k8.row.col.f32.tf32.tf32.f32 "
        "{%0,%1,%2,%3},{%4,%5,%6,%7},{%8,%9},{%0,%1,%2,%3};\n"
        : "+f"(c[0]),"+f"(c[1]),"+f"(c[2]),"+f"(c[3])
        : "r"(a[0]),"r"(a[1]),"r"(a[2]),"r"(a[3]),"r"(b[0]),"r"(b[1]));
}

// ---------------- tf32 GEMM: C[MxN] = A[MxK] @ B[KxN] ----------------
// Block tile 128x64, BK=32, 256 threads (8 warps), warp tile 32x32.
#define GAS 36   // As stride (conflict-free: 36 mod 32 = 4 -> 4g+tig distinct)
#define GBS 72   // Bs stride (72 mod 32 = 8 -> 8*tig+g distinct)
__global__ __launch_bounds__(256) void gemm_tf32(
    const float* __restrict__ A, const float* __restrict__ B,
    float* __restrict__ C, int M, int N, int K)
{
    __shared__ float As[128][GAS];
    __shared__ float Bs[32][GBS];

    const int t = threadIdx.x;
    const int w = t >> 5, lane = t & 31, g = lane >> 2, tig = lane & 3;
    const int wm = (w >> 1) * 32, wn = (w & 1) * 32;
    const int m0 = blockIdx.y * 128, n0 = blockIdx.x * 64;

    float Co[2][4][4] = {};

    for (int k0 = 0; k0 < K; k0 += 32) {
        // A tile 128x32 (cvt to tf32)
        #pragma unroll
        for (int i = 0; i < 4; i++) {
            int v = t + i * 256;                 // float4 index
            int r = v >> 3, c = (v & 7) * 4;
            float4 x = *(const float4*)&A[(size_t)(m0 + r) * K + k0 + c];
            As[r][c+0] = f2tf_f(x.x); As[r][c+1] = f2tf_f(x.y);
            As[r][c+2] = f2tf_f(x.z); As[r][c+3] = f2tf_f(x.w);
        }
        // B tile 32x64
        #pragma unroll
        for (int i = 0; i < 2; i++) {
            int v = t + i * 256;
            int r = v >> 4, c = (v & 15) * 4;
            float4 x = *(const float4*)&B[(size_t)(k0 + r) * N + n0 + c];
            Bs[r][c+0] = f2tf_f(x.x); Bs[r][c+1] = f2tf_f(x.y);
            Bs[r][c+2] = f2tf_f(x.z); Bs[r][c+3] = f2tf_f(x.w);
        }
        __syncthreads();

        #pragma unroll
        for (int ks = 0; ks < 4; ks++) {
            unsigned a[2][4], b[4][2];
            #pragma unroll
            for (int mt = 0; mt < 2; mt++) {
                int r = wm + mt * 16 + g, c = ks * 8 + tig;
                a[mt][0] = __float_as_uint(As[r    ][c    ]);
                a[mt][1] = __float_as_uint(As[r + 8][c    ]);
                a[mt][2] = __float_as_uint(As[r    ][c + 4]);
                a[mt][3] = __float_as_uint(As[r + 8][c + 4]);
            }
            #pragma unroll
            for (int nt = 0; nt < 4; nt++) {
                int c = wn + nt * 8 + g, r = ks * 8 + tig;
                b[nt][0] = __float_as_uint(Bs[r    ][c]);
                b[nt][1] = __float_as_uint(Bs[r + 4][c]);
            }
            #pragma unroll
            for (int mt = 0; mt < 2; mt++)
                #pragma unroll
                for (int nt = 0; nt < 4; nt++)
                    mma8(Co[mt][nt], a[mt], b[nt]);
        }
        __syncthreads();
    }

    #pragma unroll
    for (int mt = 0; mt < 2; mt++)
        #pragma unroll
        for (int nt = 0; nt < 4; nt++) {
            int r = m0 + wm + mt * 16 + g;
            int c = n0 + wn + nt * 8 + 2 * tig;
            *(float2*)&C[(size_t)r * N + c]       = make_float2(Co[mt][nt][0], Co[mt][nt][1]);
            *(float2*)&C[(size_t)(r + 8) * N + c] = make_float2(Co[mt][nt][2], Co[mt][nt][3]);
        }
}

// ---------------- normalize + head-scatter (outputs tf32-rounded) ----------
__global__ __launch_bounds__(256) void qkv_norm_kernel(
    const float* __restrict__ projq, const float* __restrict__ projkv,
    float* __restrict__ gq, float* __restrict__ gk, float* __restrict__ gv)
{
    int idx = blockIdx.x * blockDim.x + threadIdx.x;
    if (idx >= NTOK * NH) return;
    const int h   = idx & (NH - 1);
    const int tok = idx >> 4;
    const int b   = tok / SEQ;
    const int n   = tok - b * SEQ;
    const size_t bh = (size_t)(b * NH + h);

    // q
    {
        const float* src = projq + (size_t)tok * QCOLS + h * DKH;
        float v[16];
        #pragma unroll
        for (int i = 0; i < 4; i++) {
            float4 x = *(const float4*)&src[i*4];
            v[i*4]=x.x; v[i*4+1]=x.y; v[i*4+2]=x.z; v[i*4+3]=x.w;
        }
        float ss = 0.f;
        #pragma unroll
        for (int i = 0; i < 16; i++) ss += v[i]*v[i];
        float sc = 1.f / fmaxf(sqrtf(ss), 1e-12f);
        float* dst = gq + ((bh * SEQ) + n) * DKH;
        #pragma unroll
        for (int i = 0; i < 4; i++) {
            float4 x = make_float4(f2tf_f(v[i*4]*sc), f2tf_f(v[i*4+1]*sc),
                                   f2tf_f(v[i*4+2]*sc), f2tf_f(v[i*4+3]*sc));
            *(float4*)&dst[i*4] = x;
        }
    }
    // k
    {
        const float* src = projkv + (size_t)tok * KVCOLS + h * (DKH + DVH);
        float v[16];
        #pragma unroll
        for (int i = 0; i < 4; i++) {
            float4 x = *(const float4*)&src[i*4];
            v[i*4]=x.x; v[i*4+1]=x.y; v[i*4+2]=x.z; v[i*4+3]=x.w;
        }
        float ss = 0.f;
        #pragma unroll
        for (int i = 0; i < 16; i++) ss += v[i]*v[i];
        float sc = 1.f / fmaxf(sqrtf(ss), 1e-12f);
        float* dst = gk + ((bh * SEQ) + n) * DKH;
        #pragma unroll
        for (int i = 0; i < 4; i++) {
            float4 x = make_float4(f2tf_f(v[i*4]*sc), f2tf_f(v[i*4+1]*sc),
                                   f2tf_f(v[i*4+2]*sc), f2tf_f(v[i*4+3]*sc));
            *(float4*)&dst[i*4] = x;
        }
    }
    // v
    {
        const float* src = projkv + (size_t)tok * KVCOLS + h * (DKH + DVH) + DKH;
        float v[64];
        #pragma unroll
        for (int i = 0; i < 16; i++) {
            float4 x = *(const float4*)&src[i*4];
            v[i*4]=x.x; v[i*4+1]=x.y; v[i*4+2]=x.z; v[i*4+3]=x.w;
        }
        float ss = 0.f;
        #pragma unroll
        for (int i = 0; i < 64; i++) ss += v[i]*v[i];
        float sc = 1.f / fmaxf(sqrtf(ss), 1e-12f);
        float* dst = gv + ((bh * SEQ) + n) * DVH;
        #pragma unroll
        for (int i = 0; i < 16; i++) {
            float4 x = make_float4(f2tf_f(v[i*4]*sc), f2tf_f(v[i*4+1]*sc),
                                   f2tf_f(v[i*4+2]*sc), f2tf_f(v[i*4+3]*sc));
            *(float4*)&dst[i*4] = x;
        }
    }
}

// ---------------- fused attention (tensor cores) ----------------
// grid (SEQ/64, BATCH*NH), 128 threads (4 warps), warp tile 32x32.
#define SKS 20   // Qs/Ks stride  (20 mod 32 -> 20g+tig distinct)
#define SVS 72   // Vs stride     (8*tig+g distinct)
#define SSS 68   // Ss stride     (4g+tig distinct)
__global__ __launch_bounds__(128) void attn_mma(
    const float* __restrict__ gq, const float* __restrict__ gk,
    const float* __restrict__ gv, float* __restrict__ gao)
{
    __shared__ float Qs[64][SKS];
    __shared__ float Ks[64][SKS];
    __shared__ float Vs[64][SVS];
    __shared__ float Ss[64][SSS];
    __shared__ float rscale[64];

    const int t = threadIdx.x;
    const int w = t >> 5, lane = t & 31, g = lane >> 2, tig = lane & 3;
    const int wm = (w >> 1) * 32, wn = (w & 1) * 32;
    const int bh = blockIdx.y, q0 = blockIdx.x * 64;

    const float* qb = gq + (size_t)bh * SEQ * DKH;
    const float* kb = gk + (size_t)bh * SEQ * DKH;
    const float* vb = gv + (size_t)bh * SEQ * DVH;

    // Q tile 64x16 (contiguous 1024 floats, already tf32)
    #pragma unroll
    for (int i = 0; i < 2; i++) {
        int v = t + i * 128;
        float4 x = *(const float4*)&qb[(size_t)q0 * DKH + v * 4];
        int r = v >> 2, c = (v & 3) * 4;
        Qs[r][c]=x.x; Qs[r][c+1]=x.y; Qs[r][c+2]=x.z; Qs[r][c+3]=x.w;
    }
    __syncthreads();

    // Q fragments resident in registers for the whole key loop
    unsigned aq[2][2][4];
    #pragma unroll
    for (int mt = 0; mt < 2; mt++)
        #pragma unroll
        for (int ks = 0; ks < 2; ks++) {
            int r = wm + mt * 16 + g, c = ks * 8 + tig;
            aq[mt][ks][0] = __float_as_uint(Qs[r    ][c    ]);
            aq[mt][ks][1] = __float_as_uint(Qs[r + 8][c    ]);
            aq[mt][ks][2] = __float_as_uint(Qs[r    ][c + 4]);
            aq[mt][ks][3] = __float_as_uint(Qs[r + 8][c + 4]);
        }

    float Co[2][4][4] = {};

    for (int k0 = 0; k0 < SEQ; k0 += 64) {
        // K tile 64x16
        #pragma unroll
        for (int i = 0; i < 2; i++) {
            int v = t + i * 128;
            float4 x = *(const float4*)&kb[(size_t)k0 * DKH + v * 4];
            int r = v >> 2, c = (v & 3) * 4;
            Ks[r][c]=x.x; Ks[r][c+1]=x.y; Ks[r][c+2]=x.z; Ks[r][c+3]=x.w;
        }
        // V tile 64x64
        #pragma unroll
        for (int i = 0; i < 8; i++) {
            int v = t + i * 128;
            float4 x = *(const float4*)&vb[(size_t)k0 * DVH + v * 4];
            int r = v >> 4, c = (v & 15) * 4;
            Vs[r][c]=x.x; Vs[r][c+1]=x.y; Vs[r][c+2]=x.z; Vs[r][c+3]=x.w;
        }
        __syncthreads();

        // ---- S = Q @ K^T ----
        float Cs[2][4][4] = {};
        #pragma unroll
        for (int ks = 0; ks < 2; ks++) {
            unsigned b[4][2];
            #pragma unroll
            for (int nt = 0; nt < 4; nt++) {
                int n = wn + nt * 8 + g, c = ks * 8 + tig;
                b[nt][0] = __float_as_uint(Ks[n][c    ]);
                b[nt][1] = __float_as_uint(Ks[n][c + 4]);
            }
            #pragma unroll
            for (int mt = 0; mt < 2; mt++)
                #pragma unroll
                for (int nt = 0; nt < 4; nt++)
                    mma8(Cs[mt][nt], aq[mt][ks], b[nt]);
        }

        // relu^2 + cvt to tf32, store S[q][key]
        #pragma unroll
        for (int mt = 0; mt < 2; mt++)
            #pragma unroll
            for (int nt = 0; nt < 4; nt++) {
                int r = wm + mt * 16 + g, c = wn + nt * 8 + 2 * tig;
                float x0 = Cs[mt][nt][0]; x0 = x0 > 0.f ? x0 * x0 : 0.f;
                float x1 = Cs[mt][nt][1]; x1 = x1 > 0.f ? x1 * x1 : 0.f;
                float x2 = Cs[mt][nt][2]; x2 = x2 > 0.f ? x2 * x2 : 0.f;
                float x3 = Cs[mt][nt][3]; x3 = x3 > 0.f ? x3 * x3 : 0.f;
                *(float2*)&Ss[r    ][c] = make_float2(f2tf_f(x0), f2tf_f(x1));
                *(float2*)&Ss[r + 8][c] = make_float2(f2tf_f(x2), f2tf_f(x3));
            }
        __syncthreads();

        // ---- Out += S @ V ----
        #pragma unroll
        for (int ks = 0; ks < 8; ks++) {
            unsigned a[2][4], b[4][2];
            #pragma unroll
            for (int mt = 0; mt < 2; mt++) {
                int r = wm + mt * 16 + g, c = ks * 8 + tig;
                a[mt][0] = __float_as_uint(Ss[r    ][c    ]);
                a[mt][1] = __float_as_uint(Ss[r + 8][c    ]);
                a[mt][2] = __float_as_uint(Ss[r    ][c + 4]);
                a[mt][3] = __float_as_uint(Ss[r + 8][c + 4]);
            }
            #pragma unroll
            for (int nt = 0; nt < 4; nt++) {
                int c = wn + nt * 8 + g, r = ks * 8 + tig;
                b[nt][0] = __float_as_uint(Vs[r    ][c]);
                b[nt][1] = __float_as_uint(Vs[r + 4][c]);
            }
            #pragma unroll
            for (int mt = 0; mt < 2; mt++)
                #pragma unroll
                for (int nt = 0; nt < 4; nt++)
                    mma8(Co[mt][nt], a[mt], b[nt]);
        }
        __syncthreads();
    }

    // epilogue: dump Co into Ss (reuse as Os[q][dv]), fp32
    #pragma unroll
    for (int mt = 0; mt < 2; mt++)
        #pragma unroll
        for (int nt = 0; nt < 4; nt++) {
            int r = wm + mt * 16 + g, c = wn + nt * 8 + 2 * tig;
            *(float2*)&Ss[r    ][c] = make_float2(Co[mt][nt][0], Co[mt][nt][1]);
            *(float2*)&Ss[r + 8][c] = make_float2(Co[mt][nt][2], Co[mt][nt][3]);
        }
    __syncthreads();

    if (t < 64) {
        float ss = 0.f;
        #pragma unroll 8
        for (int j = 0; j < 64; j++) { float x = Ss[t][j]; ss += x * x; }
        float nrm = sqrtf(ss);
        rscale[t] = tanhf(nrm) / fmaxf(nrm, 1e-12f);
    }
    __syncthreads();

    {
        const int b = bh >> 4, h = bh & 15;
        int r = t >> 1, cb = (t & 1) * 32;
        float sc = rscale[r];
        float* dst = gao + (size_t)(b * SEQ + q0 + r) * OCOLS + h * DVH + cb;
        #pragma unroll
        for (int c = 0; c < 32; c += 4) {
            float4 v4 = *(float4*)&Ss[r][cb + c];
            v4.x *= sc; v4.y *= sc; v4.z *= sc; v4.w *= sc;
            *(float4*)&dst[c] = v4;
        }
    }
}

// ---------------- host launch ----------------
extern "C" void kernel_launch(void* const* d_in, const int* in_sizes, int n_in,
                              void* d_out, int out_size)
{
    const float *tokens = nullptr, *Wq = nullptr, *Wkv = nullptr, *Wout = nullptr;
    for (int i = 0; i < n_in; i++) {
        switch (in_sizes[i]) {
            case NTOK * DIM:   tokens = (const float*)d_in[i]; break;
            case DIM * QCOLS:  Wq     = (const float*)d_in[i]; break;
            case DIM * KVCOLS: Wkv    = (const float*)d_in[i]; break;
            case OCOLS * DIM:  Wout   = (const float*)d_in[i]; break;
        }
    }

    float *projq, *projkv, *qn, *kn, *vn, *ao;
    cudaGetSymbolAddress((void**)&projq,  g_projq);
    cudaGetSymbolAddress((void**)&projkv, g_projkv);
    cudaGetSymbolAddress((void**)&qn,     g_qn);
    cudaGetSymbolAddress((void**)&kn,     g_kn);
    cudaGetSymbolAddress((void**)&vn,     g_vn);
    cudaGetSymbolAddress((void**)&ao,     g_ao);

    gemm_tf32<<<dim3(QCOLS/64,  NTOK/128), 256>>>(tokens, Wq,  projq,  NTOK, QCOLS,  DIM);
    gemm_tf32<<<dim3(KVCOLS/64, NTOK/128), 256>>>(tokens, Wkv, projkv, NTOK, KVCOLS, DIM);

    qkv_norm_kernel<<<(NTOK*NH + 255)/256, 256>>>(projq, projkv, qn, kn, vn);

    attn_mma<<<dim3(SEQ/64, BATCH*NH), 128>>>(qn, kn, vn, ao);

    gemm_tf32<<<dim3(DIM/64, NTOK/128), 256>>>(ao, Wout, (float*)d_out, NTOK, DIM, OCOLS);
}

// round 3
// speedup vs baseline: 3.3484x; 1.3648x over previous
#include <cuda_runtime.h>
#include <cuda_fp16.h>
#include <cmath>

// Problem constants
#define BATCH   2
#define SEQ     2048
#define DIM     1024
#define NH      16
#define DKH     16
#define DVH     64
#define NTOK    (BATCH*SEQ)          // 4096
#define QCOLS   (NH*DKH)             // 256
#define KVCOLS  (NH*(DKH+DVH))       // 1280
#define OCOLS   (NH*DVH)             // 1024

// ---------------- scratch ----------------
__device__ float  g_projq [NTOK * QCOLS];
__device__ float  g_projkv[NTOK * KVCOLS];
__device__ __half g_qn[BATCH*NH*SEQ*DKH];
__device__ __half g_kn[BATCH*NH*SEQ*DKH];
__device__ __half g_vh[BATCH*NH*SEQ*DVH];     // [bh][seq][dv]
__device__ __half g_vt[BATCH*NH*DVH*SEQ];     // [bh][dv][seq]
__device__ float  g_ao[NTOK * OCOLS];

// ---------------- helpers ----------------
__device__ __forceinline__ unsigned packh2(float a, float b){
    __half2 h = __floats2half2_rn(a, b);
    return *(unsigned*)&h;
}

// D += A(16x16) * B(16x8), fp16 in, fp32 accum, row.col
__device__ __forceinline__ void mma16(float* c, const unsigned* a, const unsigned* b){
    asm volatile("mma.sync.aligned.m16n8k16.row.col.f32.f16.f16.f32 "
        "{%0,%1,%2,%3},{%4,%5,%6,%7},{%8,%9},{%0,%1,%2,%3};\n"
        : "+f"(c[0]),"+f"(c[1]),"+f"(c[2]),"+f"(c[3])
        : "r"(a[0]),"r"(a[1]),"r"(a[2]),"r"(a[3]),"r"(b[0]),"r"(b[1]));
}

// ---------------- fp16 GEMM: C[MxN] = A[MxK] @ B[KxN] ----------------
// Block tile 128x64, BK=32 (fp16 elems), 256 threads (8 warps), warp tile 32x32.
// Smem holds k-pair-packed u32: As[r][kp] (kp = k/2), Bs[n][kp] (transposed in-load).
#define GAS 20   // u32 stride: bank = 20g+tig -> 32 distinct
#define GBS 20
__global__ __launch_bounds__(256) void gemm_f16(
    const float* __restrict__ A, const float* __restrict__ B,
    float* __restrict__ C, int M, int N, int K)
{
    __shared__ unsigned As[128][GAS];
    __shared__ unsigned Bs[64][GBS];

    const int t = threadIdx.x;
    const int w = t >> 5, lane = t & 31, g = lane >> 2, tig = lane & 3;
    const int wm = (w >> 1) * 32, wn = (w & 1) * 32;
    const int m0 = blockIdx.y * 128, n0 = blockIdx.x * 64;

    float Co[2][4][4] = {};

    for (int k0 = 0; k0 < K; k0 += 32) {
        // A tile 128x32 f32 -> fp16 pairs.  512 (row,kgroup8) units, 2 per thread.
        #pragma unroll
        for (int i = 0; i < 2; i++) {
            int v = t + i * 256;
            int r = v >> 2, kg = v & 3;                // kg: group of 8 k
            const float* src = &A[(size_t)(m0 + r) * K + k0 + kg * 8];
            float4 x = *(const float4*)&src[0];
            float4 y = *(const float4*)&src[4];
            uint4 p = make_uint4(packh2(x.x,x.y), packh2(x.z,x.w),
                                 packh2(y.x,y.y), packh2(y.z,y.w));
            *(uint4*)&As[r][kg * 4] = p;
        }
        // B tile 32x64 f32, transpose to Bs[n][kp].  256 (kp, ngroup4) units.
        {
            int kp = t >> 4;                 // 0..15
            int n4 = (t & 15) * 4;
            const float* r0 = &B[(size_t)(k0 + 2*kp    ) * N + n0 + n4];
            const float* r1 = &B[(size_t)(k0 + 2*kp + 1) * N + n0 + n4];
            float4 lo = *(const float4*)r0;
            float4 hi = *(const float4*)r1;
            Bs[n4+0][kp] = packh2(lo.x, hi.x);
            Bs[n4+1][kp] = packh2(lo.y, hi.y);
            Bs[n4+2][kp] = packh2(lo.z, hi.z);
            Bs[n4+3][kp] = packh2(lo.w, hi.w);
        }
        __syncthreads();

        #pragma unroll
        for (int ks = 0; ks < 2; ks++) {       // two k16 steps per BK=32
            unsigned a[2][4], b[4][2];
            #pragma unroll
            for (int mt = 0; mt < 2; mt++) {
                int r = wm + mt * 16 + g, c = ks * 8 + tig;
                a[mt][0] = As[r    ][c    ];
                a[mt][1] = As[r + 8][c    ];
                a[mt][2] = As[r    ][c + 4];
                a[mt][3] = As[r + 8][c + 4];
            }
            #pragma unroll
            for (int nt = 0; nt < 4; nt++) {
                int n = wn + nt * 8 + g, c = ks * 8 + tig;
                b[nt][0] = Bs[n][c    ];
                b[nt][1] = Bs[n][c + 4];
            }
            #pragma unroll
            for (int mt = 0; mt < 2; mt++)
                #pragma unroll
                for (int nt = 0; nt < 4; nt++)
                    mma16(Co[mt][nt], a[mt], b[nt]);
        }
        __syncthreads();
    }

    #pragma unroll
    for (int mt = 0; mt < 2; mt++)
        #pragma unroll
        for (int nt = 0; nt < 4; nt++) {
            int r = m0 + wm + mt * 16 + g;
            int c = n0 + wn + nt * 8 + 2 * tig;
            *(float2*)&C[(size_t)r * N + c]       = make_float2(Co[mt][nt][0], Co[mt][nt][1]);
            *(float2*)&C[(size_t)(r + 8) * N + c] = make_float2(Co[mt][nt][2], Co[mt][nt][3]);
        }
}

// ---------------- normalize + head-scatter -> fp16 ----------------
__global__ __launch_bounds__(256) void qkv_norm_kernel(
    const float* __restrict__ projq, const float* __restrict__ projkv,
    __half* __restrict__ gq, __half* __restrict__ gk, __half* __restrict__ gv)
{
    int idx = blockIdx.x * blockDim.x + threadIdx.x;
    if (idx >= NTOK * NH) return;
    const int h   = idx & (NH - 1);
    const int tok = idx >> 4;
    const int b   = tok / SEQ;
    const int n   = tok - b * SEQ;
    const size_t bh = (size_t)(b * NH + h);

    // q
    {
        const float* src = projq + (size_t)tok * QCOLS + h * DKH;
        float v[16];
        #pragma unroll
        for (int i = 0; i < 4; i++) {
            float4 x = *(const float4*)&src[i*4];
            v[i*4]=x.x; v[i*4+1]=x.y; v[i*4+2]=x.z; v[i*4+3]=x.w;
        }
        float ss = 0.f;
        #pragma unroll
        for (int i = 0; i < 16; i++) ss += v[i]*v[i];
        float sc = 1.f / fmaxf(sqrtf(ss), 1e-12f);
        unsigned* dst = (unsigned*)(gq + ((bh * SEQ) + n) * DKH);
        #pragma unroll
        for (int i = 0; i < 8; i++)
            dst[i] = packh2(v[2*i]*sc, v[2*i+1]*sc);
    }
    // k
    {
        const float* src = projkv + (size_t)tok * KVCOLS + h * (DKH + DVH);
        float v[16];
        #pragma unroll
        for (int i = 0; i < 4; i++) {
            float4 x = *(const float4*)&src[i*4];
            v[i*4]=x.x; v[i*4+1]=x.y; v[i*4+2]=x.z; v[i*4+3]=x.w;
        }
        float ss = 0.f;
        #pragma unroll
        for (int i = 0; i < 16; i++) ss += v[i]*v[i];
        float sc = 1.f / fmaxf(sqrtf(ss), 1e-12f);
        unsigned* dst = (unsigned*)(gk + ((bh * SEQ) + n) * DKH);
        #pragma unroll
        for (int i = 0; i < 8; i++)
            dst[i] = packh2(v[2*i]*sc, v[2*i+1]*sc);
    }
    // v
    {
        const float* src = projkv + (size_t)tok * KVCOLS + h * (DKH + DVH) + DKH;
        float v[64];
        #pragma unroll
        for (int i = 0; i < 16; i++) {
            float4 x = *(const float4*)&src[i*4];
            v[i*4]=x.x; v[i*4+1]=x.y; v[i*4+2]=x.z; v[i*4+3]=x.w;
        }
        float ss = 0.f;
        #pragma unroll
        for (int i = 0; i < 64; i++) ss += v[i]*v[i];
        float sc = 1.f / fmaxf(sqrtf(ss), 1e-12f);
        unsigned* dst = (unsigned*)(gv + ((bh * SEQ) + n) * DVH);
        #pragma unroll
        for (int i = 0; i < 32; i++)
            dst[i] = packh2(v[2*i]*sc, v[2*i+1]*sc);
    }
}

// ---------------- V transpose: [bh][seq][dv] -> [bh][dv][seq] ----------------
__global__ __launch_bounds__(256) void vt_kernel(
    const __half* __restrict__ vh, __half* __restrict__ vt)
{
    __shared__ __half ts[64][72];     // pad: u32 stride 36
    const int t = threadIdx.x;
    const int bh = blockIdx.y, s0 = blockIdx.x * 64;
    const __half* src = vh + ((size_t)bh * SEQ + s0) * DVH;

    #pragma unroll
    for (int i = 0; i < 2; i++) {
        int v = t + i * 256;
        int r = v >> 3, c = (v & 7) * 8;
        *(uint4*)&ts[r][c] = *(const uint4*)&src[(size_t)r * DVH + c];
    }
    __syncthreads();

    __half* dstb = vt + (size_t)bh * DVH * SEQ;
    const int dv = t >> 2;
    const int kp0 = (t & 3) * 8;
    unsigned* drow = (unsigned*)(dstb + (size_t)dv * SEQ + s0);
    #pragma unroll
    for (int j = 0; j < 8; j++) {
        int s = 2 * (kp0 + j);
        drow[kp0 + j] = packh2(__half2float(ts[s][dv]), __half2float(ts[s+1][dv]));
    }
}

// ---------------- fused attention (fp16 tensor cores) ----------------
// grid (SEQ/64, BATCH*NH), 128 threads (4 warps), warp tile 32x32.
#define SQS 12   // Qs/Ks u32 stride (8 data + 4 pad)
#define SVS 36   // Vs/Ss u32 stride (32 data + 4 pad)
__global__ __launch_bounds__(128) void attn_f16(
    const __half* __restrict__ gq, const __half* __restrict__ gk,
    const __half* __restrict__ gvt, float* __restrict__ gao)
{
    __shared__ unsigned Qs[64][SQS];   // [q][kp of dk]
    __shared__ unsigned Ks[64][SQS];   // [key][kp of dk]
    __shared__ unsigned Vs[64][SVS];   // [dv][kp of keys]
    __shared__ unsigned Ss[64][SVS];   // [q][kp of keys] fp16
    __shared__ float Os[64][68];
    __shared__ float rscale[64];

    const int t = threadIdx.x;
    const int w = t >> 5, lane = t & 31, g = lane >> 2, tig = lane & 3;
    const int wm = (w >> 1) * 32, wn = (w & 1) * 32;
    const int bh = blockIdx.y, q0 = blockIdx.x * 64;

    const __half* qb = gq  + (size_t)bh * SEQ * DKH;
    const __half* kb = gk  + (size_t)bh * SEQ * DKH;
    const __half* vb = gvt + (size_t)bh * DVH * SEQ;

    // Q tile 64x16 fp16: 128 uint4 (one per thread)
    {
        int r = t >> 1, hf = t & 1;
        *(uint4*)&Qs[r][hf * 4] =
            *(const uint4*)&qb[(size_t)(q0 + r) * DKH + hf * 8];
    }
    __syncthreads();

    // Q fragments register-resident (K=16 -> single k16 step)
    unsigned aq[2][4];
    #pragma unroll
    for (int mt = 0; mt < 2; mt++) {
        int r = wm + mt * 16 + g;
        aq[mt][0] = Qs[r    ][tig    ];
        aq[mt][1] = Qs[r + 8][tig    ];
        aq[mt][2] = Qs[r    ][tig + 4];
        aq[mt][3] = Qs[r + 8][tig + 4];
    }

    float Co[2][4][4] = {};

    for (int k0 = 0; k0 < SEQ; k0 += 64) {
        // K tile 64x16 fp16
        {
            int r = t >> 1, hf = t & 1;
            *(uint4*)&Ks[r][hf * 4] =
                *(const uint4*)&kb[(size_t)(k0 + r) * DKH + hf * 8];
        }
        // V tile: Vt rows [64 dv][64 keys] fp16 -> Vs[dv][kp], 512 uint4
        #pragma unroll
        for (int i = 0; i < 4; i++) {
            int v = t + i * 128;
            int r = v >> 3, c = v & 7;      // c: group of 8 halfs = 4 u32
            *(uint4*)&Vs[r][c * 4] =
                *(const uint4*)&vb[(size_t)r * SEQ + k0 + c * 8];
        }
        __syncthreads();

        // ---- S = Q @ K^T  (single k16 step) ----
        float Cs[2][4][4] = {};
        {
            unsigned b[4][2];
            #pragma unroll
            for (int nt = 0; nt < 4; nt++) {
                int n = wn + nt * 8 + g;
                b[nt][0] = Ks[n][tig    ];
                b[nt][1] = Ks[n][tig + 4];
            }
            #pragma unroll
            for (int mt = 0; mt < 2; mt++)
                #pragma unroll
                for (int nt = 0; nt < 4; nt++)
                    mma16(Cs[mt][nt], aq[mt], b[nt]);
        }

        // relu^2 -> fp16 pairs -> Ss[q][kp]
        #pragma unroll
        for (int mt = 0; mt < 2; mt++)
            #pragma unroll
            for (int nt = 0; nt < 4; nt++) {
                int r = wm + mt * 16 + g;
                int c = wn / 2 + nt * 4 + tig;      // kp col
                float x0 = Cs[mt][nt][0]; x0 = x0 > 0.f ? x0 * x0 : 0.f;
                float x1 = Cs[mt][nt][1]; x1 = x1 > 0.f ? x1 * x1 : 0.f;
                float x2 = Cs[mt][nt][2]; x2 = x2 > 0.f ? x2 * x2 : 0.f;
                float x3 = Cs[mt][nt][3]; x3 = x3 > 0.f ? x3 * x3 : 0.f;
                Ss[r    ][c] = packh2(x0, x1);
                Ss[r + 8][c] = packh2(x2, x3);
            }
        __syncthreads();

        // ---- Out += S @ V  (4 k16 steps over 64 keys) ----
        #pragma unroll
        for (int ks = 0; ks < 4; ks++) {
            unsigned a[2][4], b[4][2];
            #pragma unroll
            for (int mt = 0; mt < 2; mt++) {
                int r = wm + mt * 16 + g, c = ks * 8 + tig;
                a[mt][0] = Ss[r    ][c    ];
                a[mt][1] = Ss[r + 8][c    ];
                a[mt][2] = Ss[r    ][c + 4];
                a[mt][3] = Ss[r + 8][c + 4];
            }
            #pragma unroll
            for (int nt = 0; nt < 4; nt++) {
                int n = wn + nt * 8 + g, c = ks * 8 + tig;
                b[nt][0] = Vs[n][c    ];
                b[nt][1] = Vs[n][c + 4];
            }
            #pragma unroll
            for (int mt = 0; mt < 2; mt++)
                #pragma unroll
                for (int nt = 0; nt < 4; nt++)
                    mma16(Co[mt][nt], a[mt], b[nt]);
        }
        __syncthreads();
    }

    // epilogue
    #pragma unroll
    for (int mt = 0; mt < 2; mt++)
        #pragma unroll
        for (int nt = 0; nt < 4; nt++) {
            int r = wm + mt * 16 + g, c = wn + nt * 8 + 2 * tig;
            *(float2*)&Os[r    ][c] = make_float2(Co[mt][nt][0], Co[mt][nt][1]);
            *(float2*)&Os[r + 8][c] = make_float2(Co[mt][nt][2], Co[mt][nt][3]);
        }
    __syncthreads();

    if (t < 64) {
        float ss = 0.f;
        #pragma unroll 8
        for (int j = 0; j < 64; j++) { float x = Os[t][j]; ss += x * x; }
        float nrm = sqrtf(ss);
        rscale[t] = tanhf(nrm) / fmaxf(nrm, 1e-12f);
    }
    __syncthreads();

    {
        const int b = bh >> 4, h = bh & 15;
        int r = t >> 1, cb = (t & 1) * 32;
        float sc = rscale[r];
        float* dst = gao + (size_t)(b * SEQ + q0 + r) * OCOLS + h * DVH + cb;
        #pragma unroll
        for (int c = 0; c < 32; c += 4) {
            float4 v4 = *(float4*)&Os[r][cb + c];
            v4.x *= sc; v4.y *= sc; v4.z *= sc; v4.w *= sc;
            *(float4*)&dst[c] = v4;
        }
    }
}

// ---------------- host launch ----------------
extern "C" void kernel_launch(void* const* d_in, const int* in_sizes, int n_in,
                              void* d_out, int out_size)
{
    const float *tokens = nullptr, *Wq = nullptr, *Wkv = nullptr, *Wout = nullptr;
    for (int i = 0; i < n_in; i++) {
        switch (in_sizes[i]) {
            case NTOK * DIM:   tokens = (const float*)d_in[i]; break;
            case DIM * QCOLS:  Wq     = (const float*)d_in[i]; break;
            case DIM * KVCOLS: Wkv    = (const float*)d_in[i]; break;
            case OCOLS * DIM:  Wout   = (const float*)d_in[i]; break;
        }
    }

    float *projq, *projkv, *ao;
    __half *qn, *kn, *vh, *vt;
    cudaGetSymbolAddress((void**)&projq,  g_projq);
    cudaGetSymbolAddress((void**)&projkv, g_projkv);
    cudaGetSymbolAddress((void**)&qn,     g_qn);
    cudaGetSymbolAddress((void**)&kn,     g_kn);
    cudaGetSymbolAddress((void**)&vh,     g_vh);
    cudaGetSymbolAddress((void**)&vt,     g_vt);
    cudaGetSymbolAddress((void**)&ao,     g_ao);

    gemm_f16<<<dim3(QCOLS/64,  NTOK/128), 256>>>(tokens, Wq,  projq,  NTOK, QCOLS,  DIM);
    gemm_f16<<<dim3(KVCOLS/64, NTOK/128), 256>>>(tokens, Wkv, projkv, NTOK, KVCOLS, DIM);

    qkv_norm_kernel<<<(NTOK*NH + 255)/256, 256>>>(projq, projkv, qn, kn, vh);
    vt_kernel<<<dim3(SEQ/64, BATCH*NH), 256>>>(vh, vt);

    attn_f16<<<dim3(SEQ/64, BATCH*NH), 128>>>(qn, kn, vt, ao);

    gemm_f16<<<dim3(DIM/64, NTOK/128), 256>>>(ao, Wout, (float*)d_out, NTOK, DIM, OCOLS);
}

// round 4
// speedup vs baseline: 4.3913x; 1.3115x over previous
#include <cuda_runtime.h>
#include <cuda_fp16.h>
#include <cmath>

// Problem constants
#define BATCH   2
#define SEQ     2048
#define DIM     1024
#define NH      16
#define DKH     16
#define DVH     64
#define NTOK    (BATCH*SEQ)          // 4096
#define QCOLS   (NH*DKH)             // 256
#define KVCOLS  (NH*(DKH+DVH))       // 1280
#define OCOLS   (NH*DVH)             // 1024

// ---------------- scratch ----------------
__device__ __half g_tokh[NTOK * DIM];
__device__ __half g_wqt [QCOLS * DIM];     // Wq^T  [n][k] fp16
__device__ __half g_wkvt[KVCOLS * DIM];    // Wkv^T [n][k]
__device__ __half g_wot [DIM * OCOLS];     // Wout^T[n][k]
__device__ float  g_projq [NTOK * QCOLS];
__device__ float  g_projkv[NTOK * KVCOLS];
__device__ __half g_qn[BATCH*NH*SEQ*DKH];
__device__ __half g_kn[BATCH*NH*SEQ*DKH];
__device__ __half g_vh[BATCH*NH*SEQ*DVH];  // [bh][seq][dv]
__device__ __half g_aoh[NTOK * OCOLS];     // attention out, fp16

// ---------------- helpers ----------------
__device__ __forceinline__ unsigned packh2(float a, float b){
    __half2 h = __floats2half2_rn(a, b);
    return *(unsigned*)&h;
}
__device__ __forceinline__ unsigned sptr(const void* p){
    return (unsigned)__cvta_generic_to_shared(p);
}
__device__ __forceinline__ void ldm4(unsigned r[4], unsigned a){
    asm volatile("ldmatrix.sync.aligned.m8n8.x4.shared.b16 {%0,%1,%2,%3}, [%4];"
        : "=r"(r[0]),"=r"(r[1]),"=r"(r[2]),"=r"(r[3]) : "r"(a));
}
__device__ __forceinline__ void ldm4t(unsigned r[4], unsigned a){
    asm volatile("ldmatrix.sync.aligned.m8n8.x4.trans.shared.b16 {%0,%1,%2,%3}, [%4];"
        : "=r"(r[0]),"=r"(r[1]),"=r"(r[2]),"=r"(r[3]) : "r"(a));
}
__device__ __forceinline__ void stm4(unsigned a, const unsigned r[4]){
    asm volatile("stmatrix.sync.aligned.m8n8.x4.shared.b16 [%0], {%1,%2,%3,%4};"
        :: "r"(a), "r"(r[0]),"r"(r[1]),"r"(r[2]),"r"(r[3]) : "memory");
}
// D += A(16x16) * B(16x8), fp16 in, fp32 accum, row.col
__device__ __forceinline__ void mma16(float* c, const unsigned* a, const unsigned* b){
    asm volatile("mma.sync.aligned.m16n8k16.row.col.f32.f16.f16.f32 "
        "{%0,%1,%2,%3},{%4,%5,%6,%7},{%8,%9},{%0,%1,%2,%3};\n"
        : "+f"(c[0]),"+f"(c[1]),"+f"(c[2]),"+f"(c[3])
        : "r"(a[0]),"r"(a[1]),"r"(a[2]),"r"(a[3]),"r"(b[0]),"r"(b[1]));
}

// ---------------- prep: f32 -> f16 elementwise ----------------
__global__ __launch_bounds__(256) void cvt_f2h(const float* __restrict__ src,
                                              __half* __restrict__ dst, int n8)
{
    int i = blockIdx.x * blockDim.x + threadIdx.x;
    if (i >= n8) return;
    float4 a = ((const float4*)src)[2*i];
    float4 b = ((const float4*)src)[2*i+1];
    uint4 p = make_uint4(packh2(a.x,a.y), packh2(a.z,a.w),
                         packh2(b.x,b.y), packh2(b.z,b.w));
    ((uint4*)dst)[i] = p;
}

// ---------------- prep: W[K][N] f32 -> Wt[N][K] f16 ----------------
__global__ __launch_bounds__(256) void wtrans(const float* __restrict__ W,
                                              __half* __restrict__ Wt, int N, int K)
{
    __shared__ float ts[32][33];
    const int n0 = blockIdx.x * 32, k0 = blockIdx.y * 32;
    const int tx = threadIdx.x & 31, ty = threadIdx.x >> 5;
    #pragma unroll
    for (int i = 0; i < 32; i += 8)
        ts[ty + i][tx] = W[(size_t)(k0 + ty + i) * N + n0 + tx];
    __syncthreads();
    #pragma unroll
    for (int i = 0; i < 32; i += 8) {
        int n = ty + i;
        Wt[(size_t)(n0 + n) * K + k0 + tx] = __float2half(ts[tx][n]);
    }
}

// ---------------- fp16 GEMM: C[MxN] = A[MxK] @ Bt[N][K]^T ----------------
// Block 128x64, BK=32, 256 threads (8 warps), warp tile 32x32, ldmatrix frags.
#define GAS 20   // u32 stride (16 data + 4 pad)
__global__ __launch_bounds__(256) void gemm_f16(
    const __half* __restrict__ A, const __half* __restrict__ Bt,
    float* __restrict__ C, int M, int N, int K)
{
    __shared__ unsigned As[128][GAS];
    __shared__ unsigned Bs[64][GAS];

    const int t = threadIdx.x;
    const int w = t >> 5, lane = t & 31, g = lane >> 2, tig = lane & 3;
    const int wm = (w >> 1) * 32, wn = (w & 1) * 32;
    const int m0 = blockIdx.y * 128, n0 = blockIdx.x * 64;
    const int li = lane & 7, lj = lane >> 3;

    const unsigned adrA0 = sptr(&As[wm      + (lj & 1) * 8 + li][(lj >> 1) * 4]);
    const unsigned adrA1 = sptr(&As[wm + 16 + (lj & 1) * 8 + li][(lj >> 1) * 4]);
    const unsigned adrB  = sptr(&Bs[wn + lj * 8 + li][0]);

    float Co[2][4][4] = {};

    for (int k0 = 0; k0 < K; k0 += 32) {
        #pragma unroll
        for (int i2 = 0; i2 < 2; i2++) {          // A tile 128x32
            int v = t + i2 * 256;
            int r = v >> 2, c4 = v & 3;
            *(uint4*)&As[r][c4 * 4] =
                *(const uint4*)&A[(size_t)(m0 + r) * K + k0 + c4 * 8];
        }
        {                                          // B tile 64x32
            int r = t >> 2, c4 = t & 3;
            *(uint4*)&Bs[r][c4 * 4] =
                *(const uint4*)&Bt[(size_t)(n0 + r) * K + k0 + c4 * 8];
        }
        __syncthreads();

        #pragma unroll
        for (int ks = 0; ks < 2; ks++) {
            unsigned cb = ks * 32;                 // 8 u32 per kstep
            unsigned a[2][4], b0[4], b1[4];
            ldm4(a[0], adrA0 + cb);
            ldm4(a[1], adrA1 + cb);
            ldm4(b0, adrB + cb);
            ldm4(b1, adrB + cb + 16);
            #pragma unroll
            for (int nt = 0; nt < 4; nt++) {
                unsigned b[2] = { b0[nt], b1[nt] };
                mma16(Co[0][nt], a[0], b);
                mma16(Co[1][nt], a[1], b);
            }
        }
        __syncthreads();
    }

    #pragma unroll
    for (int mt = 0; mt < 2; mt++)
        #pragma unroll
        for (int nt = 0; nt < 4; nt++) {
            int r = m0 + wm + mt * 16 + g;
            int c = n0 + wn + nt * 8 + 2 * tig;
            *(float2*)&C[(size_t)r * N + c]       = make_float2(Co[mt][nt][0], Co[mt][nt][1]);
            *(float2*)&C[(size_t)(r + 8) * N + c] = make_float2(Co[mt][nt][2], Co[mt][nt][3]);
        }
}

// ---------------- normalize + head-scatter -> fp16 ----------------
__global__ __launch_bounds__(256) void qkv_norm_kernel(
    const float* __restrict__ projq, const float* __restrict__ projkv,
    __half* __restrict__ gq, __half* __restrict__ gk, __half* __restrict__ gv)
{
    int idx = blockIdx.x * blockDim.x + threadIdx.x;
    if (idx >= NTOK * NH) return;
    const int h   = idx & (NH - 1);
    const int tok = idx >> 4;
    const int b   = tok / SEQ;
    const int n   = tok - b * SEQ;
    const size_t bh = (size_t)(b * NH + h);

    {   // q
        const float* src = projq + (size_t)tok * QCOLS + h * DKH;
        float v[16];
        #pragma unroll
        for (int i = 0; i < 4; i++) {
            float4 x = *(const float4*)&src[i*4];
            v[i*4]=x.x; v[i*4+1]=x.y; v[i*4+2]=x.z; v[i*4+3]=x.w;
        }
        float ss = 0.f;
        #pragma unroll
        for (int i = 0; i < 16; i++) ss += v[i]*v[i];
        float sc = 1.f / fmaxf(sqrtf(ss), 1e-12f);
        unsigned* dst = (unsigned*)(gq + ((bh * SEQ) + n) * DKH);
        #pragma unroll
        for (int i = 0; i < 8; i++) dst[i] = packh2(v[2*i]*sc, v[2*i+1]*sc);
    }
    {   // k
        const float* src = projkv + (size_t)tok * KVCOLS + h * (DKH + DVH);
        float v[16];
        #pragma unroll
        for (int i = 0; i < 4; i++) {
            float4 x = *(const float4*)&src[i*4];
            v[i*4]=x.x; v[i*4+1]=x.y; v[i*4+2]=x.z; v[i*4+3]=x.w;
        }
        float ss = 0.f;
        #pragma unroll
        for (int i = 0; i < 16; i++) ss += v[i]*v[i];
        float sc = 1.f / fmaxf(sqrtf(ss), 1e-12f);
        unsigned* dst = (unsigned*)(gk + ((bh * SEQ) + n) * DKH);
        #pragma unroll
        for (int i = 0; i < 8; i++) dst[i] = packh2(v[2*i]*sc, v[2*i+1]*sc);
    }
    {   // v
        const float* src = projkv + (size_t)tok * KVCOLS + h * (DKH + DVH) + DKH;
        float v[64];
        #pragma unroll
        for (int i = 0; i < 16; i++) {
            float4 x = *(const float4*)&src[i*4];
            v[i*4]=x.x; v[i*4+1]=x.y; v[i*4+2]=x.z; v[i*4+3]=x.w;
        }
        float ss = 0.f;
        #pragma unroll
        for (int i = 0; i < 64; i++) ss += v[i]*v[i];
        float sc = 1.f / fmaxf(sqrtf(ss), 1e-12f);
        unsigned* dst = (unsigned*)(gv + ((bh * SEQ) + n) * DVH);
        #pragma unroll
        for (int i = 0; i < 32; i++) dst[i] = packh2(v[2*i]*sc, v[2*i+1]*sc);
    }
}

// ---------------- fused attention (fp16, ldmatrix/stmatrix) ----------------
// grid (SEQ/128, BATCH*NH), 256 threads (8 warps), warp tile 32x32 of 128x64 out.
#define AQS 12   // Qs/Ks u32 stride
#define AVS 72   // Vs half stride
#define ASS 36   // Ss u32 stride
__global__ __launch_bounds__(256) void attn_f16(
    const __half* __restrict__ gq, const __half* __restrict__ gk,
    const __half* __restrict__ gv, __half* __restrict__ gao)
{
    __shared__ unsigned Qs[128][AQS];   // [q][kp of dk]
    __shared__ unsigned Ks[64][AQS];    // [key][kp of dk]
    __shared__ __half   Vs[64][AVS];    // [key][dv]
    __shared__ unsigned Ss[128][ASS];   // [q][kp of keys] fp16
    __shared__ float    prt[128][2];
    __shared__ float    rscale[128];

    const int t = threadIdx.x;
    const int w = t >> 5, lane = t & 31, g = lane >> 2, tig = lane & 3;
    const int wm = (w >> 1) * 32, wn = (w & 1) * 32;
    const int bh = blockIdx.y, q0 = blockIdx.x * 128;
    const int li = lane & 7, lj = lane >> 3;

    const __half* qb = gq + (size_t)bh * SEQ * DKH;
    const __half* kb = gk + (size_t)bh * SEQ * DKH;
    const __half* vb = gv + (size_t)bh * SEQ * DVH;

    // Q tile 128x16: 256 uint4, one per thread
    {
        int r = t >> 1, hf = t & 1;
        *(uint4*)&Qs[r][hf * 4] = *(const uint4*)&qb[(size_t)(q0 + r) * DKH + hf * 8];
    }
    __syncthreads();

    // ldmatrix base addresses
    const unsigned adrQ0  = sptr(&Qs[wm      + (lj & 1) * 8 + li][(lj >> 1) * 4]);
    const unsigned adrQ1  = adrQ0 + 16 * AQS * 4;
    const unsigned adrK   = sptr(&Ks[wn + lj * 8 + li][0]);
    const unsigned adrSst = sptr(&Ss[wm + li][wn / 2 + lj * 4]);
    const unsigned adrSa0 = sptr(&Ss[wm      + (lj & 1) * 8 + li][(lj >> 1) * 4]);
    const unsigned adrSa1 = adrSa0 + 16 * ASS * 4;
    const unsigned adrV   = sptr(&Vs[(lj & 1) * 8 + li][wn + (lj >> 1) * 8]);

    unsigned aq[2][4];
    ldm4(aq[0], adrQ0);
    ldm4(aq[1], adrQ1);

    float Co[2][4][4] = {};

    for (int k0 = 0; k0 < SEQ; k0 += 64) {
        if (t < 128) {                          // K tile 64x16
            int r = t >> 1, hf = t & 1;
            *(uint4*)&Ks[r][hf * 4] = *(const uint4*)&kb[(size_t)(k0 + r) * DKH + hf * 8];
        }
        #pragma unroll
        for (int i2 = 0; i2 < 2; i2++) {        // V tile 64x64
            int v = t + i2 * 256;
            int r = v >> 3, c = (v & 7) * 8;
            *(uint4*)&Vs[r][c] = *(const uint4*)&vb[(size_t)(k0 + r) * DVH + c];
        }
        __syncthreads();

        // ---- S = Q @ K^T (single k16 step) ----
        float Cs[2][4][4] = {};
        {
            unsigned b0[4], b1[4];
            ldm4(b0, adrK);
            ldm4(b1, adrK + 16);
            #pragma unroll
            for (int nt = 0; nt < 4; nt++) {
                unsigned b[2] = { b0[nt], b1[nt] };
                mma16(Cs[0][nt], aq[0], b);
                mma16(Cs[1][nt], aq[1], b);
            }
        }

        // relu^2 -> fp16 -> Ss via stmatrix (4 ops)
        #pragma unroll
        for (int mt = 0; mt < 2; mt++)
            #pragma unroll
            for (int h2 = 0; h2 < 2; h2++) {
                unsigned d[4];
                #pragma unroll
                for (int nt = 0; nt < 4; nt++) {
                    float x0 = Cs[mt][nt][2*h2    ]; x0 = x0 > 0.f ? x0 * x0 : 0.f;
                    float x1 = Cs[mt][nt][2*h2 + 1]; x1 = x1 > 0.f ? x1 * x1 : 0.f;
                    d[nt] = packh2(x0, x1);
                }
                stm4(adrSst + (mt * 16 + h2 * 8) * ASS * 4, d);
            }
        __syncthreads();

        // ---- Out += S @ V (4 k16 steps) ----
        #pragma unroll
        for (int ks = 0; ks < 4; ks++) {
            unsigned a0[4], a1[4], v0[4], v1[4];
            ldm4(a0, adrSa0 + ks * 32);
            ldm4(a1, adrSa1 + ks * 32);
            ldm4t(v0, adrV + ks * 16 * AVS * 2);        // b[0],b[1]
            ldm4t(v1, adrV + ks * 16 * AVS * 2 + 32);   // b[2],b[3]
            #pragma unroll
            for (int nt = 0; nt < 4; nt++) {
                unsigned b[2];
                if (nt < 2) { b[0] = v0[2*nt]; b[1] = v0[2*nt+1]; }
                else        { b[0] = v1[2*(nt-2)]; b[1] = v1[2*(nt-2)+1]; }
                mma16(Co[0][nt], a0, b);
                mma16(Co[1][nt], a1, b);
            }
        }
        __syncthreads();
    }

    // ---- epilogue: row sum-of-squares via shuffle, then tanh-norm write ----
    #pragma unroll
    for (int mt = 0; mt < 2; mt++) {
        float s0 = 0.f, s1 = 0.f;
        #pragma unroll
        for (int nt = 0; nt < 4; nt++) {
            s0 += Co[mt][nt][0]*Co[mt][nt][0] + Co[mt][nt][1]*Co[mt][nt][1];
            s1 += Co[mt][nt][2]*Co[mt][nt][2] + Co[mt][nt][3]*Co[mt][nt][3];
        }
        s0 += __shfl_xor_sync(0xffffffffu, s0, 1);
        s0 += __shfl_xor_sync(0xffffffffu, s0, 2);
        s1 += __shfl_xor_sync(0xffffffffu, s1, 1);
        s1 += __shfl_xor_sync(0xffffffffu, s1, 2);
        if (tig == 0) {
            prt[wm + mt * 16 + g    ][w & 1] = s0;
            prt[wm + mt * 16 + 8 + g][w & 1] = s1;
        }
    }
    __syncthreads();
    if (t < 128) {
        float ss = prt[t][0] + prt[t][1];
        float nrm = sqrtf(ss);
        rscale[t] = tanhf(nrm) / fmaxf(nrm, 1e-12f);
    }
    __syncthreads();

    {
        const int b_ = bh >> 4, h_ = bh & 15;
        #pragma unroll
        for (int mt = 0; mt < 2; mt++) {
            int r = wm + mt * 16 + g;
            float sc0 = rscale[r], sc1 = rscale[r + 8];
            #pragma unroll
            for (int nt = 0; nt < 4; nt++) {
                size_t base = (size_t)(b_ * SEQ + q0 + r) * OCOLS + h_ * DVH + wn + nt * 8 + 2 * tig;
                *(unsigned*)&gao[base] =
                    packh2(Co[mt][nt][0] * sc0, Co[mt][nt][1] * sc0);
                *(unsigned*)&gao[base + 8 * OCOLS] =
                    packh2(Co[mt][nt][2] * sc1, Co[mt][nt][3] * sc1);
            }
        }
    }
}

// ---------------- host launch ----------------
extern "C" void kernel_launch(void* const* d_in, const int* in_sizes, int n_in,
                              void* d_out, int out_size)
{
    const float *tokens = nullptr, *Wq = nullptr, *Wkv = nullptr, *Wout = nullptr;
    for (int i = 0; i < n_in; i++) {
        switch (in_sizes[i]) {
            case NTOK * DIM:   tokens = (const float*)d_in[i]; break;
            case DIM * QCOLS:  Wq     = (const float*)d_in[i]; break;
            case DIM * KVCOLS: Wkv    = (const float*)d_in[i]; break;
            case OCOLS * DIM:  Wout   = (const float*)d_in[i]; break;
        }
    }

    __half *tokh, *wqt, *wkvt, *wot, *qn, *kn, *vh, *aoh;
    float *projq, *projkv;
    cudaGetSymbolAddress((void**)&tokh,   g_tokh);
    cudaGetSymbolAddress((void**)&wqt,    g_wqt);
    cudaGetSymbolAddress((void**)&wkvt,   g_wkvt);
    cudaGetSymbolAddress((void**)&wot,    g_wot);
    cudaGetSymbolAddress((void**)&projq,  g_projq);
    cudaGetSymbolAddress((void**)&projkv, g_projkv);
    cudaGetSymbolAddress((void**)&qn,     g_qn);
    cudaGetSymbolAddress((void**)&kn,     g_kn);
    cudaGetSymbolAddress((void**)&vh,     g_vh);
    cudaGetSymbolAddress((void**)&aoh,    g_aoh);

    // prep: fp16 conversions + weight transposes
    cvt_f2h<<<(NTOK*DIM/8 + 255)/256, 256>>>(tokens, tokh, NTOK*DIM/8);
    wtrans<<<dim3(QCOLS/32,  DIM/32), 256>>>(Wq,   wqt,  QCOLS,  DIM);
    wtrans<<<dim3(KVCOLS/32, DIM/32), 256>>>(Wkv,  wkvt, KVCOLS, DIM);
    wtrans<<<dim3(OCOLS/32,  DIM/32), 256>>>(Wout, wot,  DIM,    OCOLS);
    // NOTE: Wout is [OCOLS x DIM] row-major (K=OCOLS rows, N=DIM cols) -> wtrans(N=DIM,K=OCOLS)

    // projections
    gemm_f16<<<dim3(QCOLS/64,  NTOK/128), 256>>>(tokh, wqt,  projq,  NTOK, QCOLS,  DIM);
    gemm_f16<<<dim3(KVCOLS/64, NTOK/128), 256>>>(tokh, wkvt, projkv, NTOK, KVCOLS, DIM);

    qkv_norm_kernel<<<(NTOK*NH + 255)/256, 256>>>(projq, projkv, qn, kn, vh);

    attn_f16<<<dim3(SEQ/128, BATCH*NH), 256>>>(qn, kn, vh, aoh);

    gemm_f16<<<dim3(DIM/64, NTOK/128), 256>>>(aoh, wot, (float*)d_out, NTOK, DIM, OCOLS);
}

// round 5
// speedup vs baseline: 6.3528x; 1.4467x over previous
#include <cuda_runtime.h>
#include <cuda_fp16.h>
#include <cmath>

// Problem constants
#define BATCH   2
#define SEQ     2048
#define DIM     1024
#define NH      16
#define DKH     16
#define DVH     64
#define NTOK    (BATCH*SEQ)          // 4096
#define QCOLS   (NH*DKH)             // 256
#define KVCOLS  (NH*(DKH+DVH))       // 1280
#define OCOLS   (NH*DVH)             // 1024
#define PCOLS   1536                 // 256 q + 256 k + 1024 v (permuted)

// ---------------- scratch ----------------
__device__ __half g_tokh[NTOK * DIM];
__device__ __half g_wc  [PCOLS * DIM];     // combined permuted W^T [n][k]
__device__ __half g_wot [DIM * OCOLS];     // Wout^T [n][k]
__device__ __half g_qn[BATCH*NH*SEQ*DKH];
__device__ __half g_kn[BATCH*NH*SEQ*DKH];
__device__ __half g_vh[BATCH*NH*SEQ*DVH];
__device__ __half g_aoh[NTOK * OCOLS];

// ---------------- helpers ----------------
__device__ __forceinline__ unsigned packh2(float a, float b){
    __half2 h = __floats2half2_rn(a, b);
    return *(unsigned*)&h;
}
__device__ __forceinline__ unsigned sptr(const void* p){
    return (unsigned)__cvta_generic_to_shared(p);
}
__device__ __forceinline__ void ldm4(unsigned r[4], unsigned a){
    asm volatile("ldmatrix.sync.aligned.m8n8.x4.shared.b16 {%0,%1,%2,%3}, [%4];"
        : "=r"(r[0]),"=r"(r[1]),"=r"(r[2]),"=r"(r[3]) : "r"(a));
}
__device__ __forceinline__ void ldm4t(unsigned r[4], unsigned a){
    asm volatile("ldmatrix.sync.aligned.m8n8.x4.trans.shared.b16 {%0,%1,%2,%3}, [%4];"
        : "=r"(r[0]),"=r"(r[1]),"=r"(r[2]),"=r"(r[3]) : "r"(a));
}
__device__ __forceinline__ void mma16(float* c, const unsigned* a, const unsigned* b){
    asm volatile("mma.sync.aligned.m16n8k16.row.col.f32.f16.f16.f32 "
        "{%0,%1,%2,%3},{%4,%5,%6,%7},{%8,%9},{%0,%1,%2,%3};\n"
        : "+f"(c[0]),"+f"(c[1]),"+f"(c[2]),"+f"(c[3])
        : "r"(a[0]),"r"(a[1]),"r"(a[2]),"r"(a[3]),"r"(b[0]),"r"(b[1]));
}
__device__ __forceinline__ void cpa16(unsigned dst, const void* src){
    asm volatile("cp.async.cg.shared.global [%0], [%1], 16;" :: "r"(dst), "l"(src));
}
#define CP_COMMIT() asm volatile("cp.async.commit_group;" ::: "memory")
#define CP_WAIT0()  asm volatile("cp.async.wait_group 0;" ::: "memory")

// ---------------- prep: f32 -> f16 elementwise ----------------
__global__ __launch_bounds__(256) void cvt_f2h(const float* __restrict__ src,
                                              __half* __restrict__ dst, int n8)
{
    int i = blockIdx.x * blockDim.x + threadIdx.x;
    if (i >= n8) return;
    float4 a = ((const float4*)src)[2*i];
    float4 b = ((const float4*)src)[2*i+1];
    uint4 p = make_uint4(packh2(a.x,a.y), packh2(a.z,a.w),
                         packh2(b.x,b.y), packh2(b.z,b.w));
    ((uint4*)dst)[i] = p;
}

// ---------------- prep: combined permuted weight Wc^T[1536][1024] ----------
__global__ __launch_bounds__(256) void wprep(const float* __restrict__ Wq,
                                             const float* __restrict__ Wkv,
                                             __half* __restrict__ Wc)
{
    __shared__ float ts[32][33];
    const int n0 = blockIdx.x * 32, k0 = blockIdx.y * 32;
    const int tx = threadIdx.x & 31, ty = threadIdx.x >> 5;
    {
        const int n = n0 + tx;
        const float* W; int c, ld;
        if (n < 256)      { W = Wq;  ld = QCOLS;  c = n; }
        else if (n < 512) { int j = n - 256; W = Wkv; ld = KVCOLS; c = (j >> 4) * 80 + (j & 15); }
        else              { int j = n - 512; W = Wkv; ld = KVCOLS; c = (j >> 6) * 80 + 16 + (j & 63); }
        #pragma unroll
        for (int i = 0; i < 32; i += 8)
            ts[ty + i][tx] = W[(size_t)(k0 + ty + i) * ld + c];
    }
    __syncthreads();
    #pragma unroll
    for (int i = 0; i < 32; i += 8)
        Wc[(size_t)(n0 + ty + i) * DIM + k0 + tx] = __float2half(ts[tx][ty + i]);
}

// ---------------- prep: Wout[K][N] f32 -> Wt[N][K] f16 ----------------
__global__ __launch_bounds__(256) void wtrans(const float* __restrict__ W,
                                              __half* __restrict__ Wt, int N, int K)
{
    __shared__ float ts[32][33];
    const int n0 = blockIdx.x * 32, k0 = blockIdx.y * 32;
    const int tx = threadIdx.x & 31, ty = threadIdx.x >> 5;
    #pragma unroll
    for (int i = 0; i < 32; i += 8)
        ts[ty + i][tx] = W[(size_t)(k0 + ty + i) * N + n0 + tx];
    __syncthreads();
    #pragma unroll
    for (int i = 0; i < 32; i += 8)
        Wt[(size_t)(n0 + ty + i) * K + k0 + tx] = __float2half(ts[tx][ty + i]);
}

// ---------------- fused projection GEMM + l2norm + head scatter ------------
// C[4096 x 1536] = tokh @ Wc^T, block 128x64, 256 thr, cp.async double buffer.
#define GAS 20
__global__ __launch_bounds__(256) void proj_gemm(
    const __half* __restrict__ A, const __half* __restrict__ Bt,
    __half* __restrict__ gq, __half* __restrict__ gk, __half* __restrict__ gv)
{
    __shared__ unsigned As[2][128][GAS];
    __shared__ unsigned Bs[2][64][GAS];
    __shared__ float sq[128][4];

    const int t = threadIdx.x;
    const int w = t >> 5, lane = t & 31, g = lane >> 2, tig = lane & 3;
    const int wm = (w >> 1) * 32, wn = (w & 1) * 32;
    const int m0 = blockIdx.y * 128, n0 = blockIdx.x * 64;
    const int li = lane & 7, lj = lane >> 3;

    const unsigned ABUF = 128 * GAS * 4, BBUF = 64 * GAS * 4;
    const unsigned adrA0 = sptr(&As[0][wm + (lj & 1) * 8 + li][(lj >> 1) * 4]);
    const unsigned adrA1 = adrA0 + 16 * GAS * 4;
    const unsigned adrB  = sptr(&Bs[0][wn + lj * 8 + li][0]);

    // tile loaders
    const int ar = t >> 2, ac4 = t & 3;
    #define PROJ_LOAD(k0_, buf_) do {                                           \
        cpa16(sptr(&As[buf_][ar][ac4*4]),       &A[(size_t)(m0+ar)*DIM + (k0_) + ac4*8]); \
        cpa16(sptr(&As[buf_][ar+64][ac4*4]),    &A[(size_t)(m0+ar+64)*DIM + (k0_) + ac4*8]); \
        cpa16(sptr(&Bs[buf_][ar][ac4*4]),       &Bt[(size_t)(n0+ar)*DIM + (k0_) + ac4*8]); \
    } while(0)

    PROJ_LOAD(0, 0);
    CP_COMMIT();

    float Co[2][4][4] = {};
    const int KT = DIM / 32;
    for (int kt = 0; kt < KT; kt++) {
        CP_WAIT0();
        __syncthreads();
        if (kt + 1 < KT) { PROJ_LOAD((kt + 1) * 32, (kt + 1) & 1); CP_COMMIT(); }
        const unsigned oa = (kt & 1) * ABUF, ob = (kt & 1) * BBUF;

        #pragma unroll
        for (int ks = 0; ks < 2; ks++) {
            unsigned cb = ks * 32;
            unsigned a0[4], a1[4], b0[4], b1[4];
            ldm4(a0, adrA0 + oa + cb);
            ldm4(a1, adrA1 + oa + cb);
            ldm4(b0, adrB + ob + cb);
            ldm4(b1, adrB + ob + cb + 16);
            #pragma unroll
            for (int nt = 0; nt < 4; nt++) {
                unsigned b[2] = { b0[nt], b1[nt] };
                mma16(Co[0][nt], a0, b);
                mma16(Co[1][nt], a1, b);
            }
        }
        __syncthreads();
    }

    // ---- epilogue: group sums of squares ----
    #pragma unroll
    for (int mt = 0; mt < 2; mt++) {
        float pA0 = 0, pA1 = 0, pB0 = 0, pB1 = 0;
        #pragma unroll
        for (int nt = 0; nt < 2; nt++) {
            pA0 += Co[mt][nt][0]*Co[mt][nt][0] + Co[mt][nt][1]*Co[mt][nt][1];
            pA1 += Co[mt][nt][2]*Co[mt][nt][2] + Co[mt][nt][3]*Co[mt][nt][3];
            pB0 += Co[mt][nt+2][0]*Co[mt][nt+2][0] + Co[mt][nt+2][1]*Co[mt][nt+2][1];
            pB1 += Co[mt][nt+2][2]*Co[mt][nt+2][2] + Co[mt][nt+2][3]*Co[mt][nt+2][3];
        }
        pA0 += __shfl_xor_sync(~0u, pA0, 1); pA0 += __shfl_xor_sync(~0u, pA0, 2);
        pA1 += __shfl_xor_sync(~0u, pA1, 1); pA1 += __shfl_xor_sync(~0u, pA1, 2);
        pB0 += __shfl_xor_sync(~0u, pB0, 1); pB0 += __shfl_xor_sync(~0u, pB0, 2);
        pB1 += __shfl_xor_sync(~0u, pB1, 1); pB1 += __shfl_xor_sync(~0u, pB1, 2);
        if (tig == 0) {
            int r = wm + mt * 16 + g;
            sq[r    ][2*(w&1)    ] = pA0;
            sq[r    ][2*(w&1) + 1] = pB0;
            sq[r + 8][2*(w&1)    ] = pA1;
            sq[r + 8][2*(w&1) + 1] = pB1;
        }
    }
    __syncthreads();

    const int region = (n0 < 256) ? 0 : (n0 < 512 ? 1 : 2);
    #pragma unroll
    for (int mt = 0; mt < 2; mt++)
        #pragma unroll
        for (int rh = 0; rh < 2; rh++) {
            const int r = wm + mt * 16 + g + rh * 8;
            const int m = m0 + r;
            const int b_ = m >> 11, seq = m & (SEQ - 1);
            float scv = 0.f;
            if (region == 2) {
                float ss = sq[r][0] + sq[r][1] + sq[r][2] + sq[r][3];
                scv = 1.f / fmaxf(sqrtf(ss), 1e-12f);
            }
            #pragma unroll
            for (int nt = 0; nt < 4; nt++) {
                float sc;
                if (region == 2) sc = scv;
                else {
                    int grp = 2 * (w & 1) + (nt >> 1);
                    sc = 1.f / fmaxf(sqrtf(sq[r][grp]), 1e-12f);
                }
                const int n = n0 + wn + nt * 8 + 2 * tig;
                float x0 = Co[mt][nt][2*rh    ] * sc;
                float x1 = Co[mt][nt][2*rh + 1] * sc;
                unsigned pv = packh2(x0, x1);
                if (region == 0) {
                    int h = n >> 4, d = n & 15;
                    *(unsigned*)&gq[((size_t)(b_*NH + h) * SEQ + seq) * DKH + d] = pv;
                } else if (region == 1) {
                    int j = n - 256, h = j >> 4, d = j & 15;
                    *(unsigned*)&gk[((size_t)(b_*NH + h) * SEQ + seq) * DKH + d] = pv;
                } else {
                    int j = n - 512, h = j >> 6, d = j & 63;
                    *(unsigned*)&gv[((size_t)(b_*NH + h) * SEQ + seq) * DVH + d] = pv;
                }
            }
        }
}

// ---------------- final GEMM: C_f32[MxN] = A @ Bt^T, cp.async pipelined -----
__global__ __launch_bounds__(256) void gemm_f16(
    const __half* __restrict__ A, const __half* __restrict__ Bt,
    float* __restrict__ C, int M, int N, int K)
{
    __shared__ unsigned As[2][128][GAS];
    __shared__ unsigned Bs[2][64][GAS];

    const int t = threadIdx.x;
    const int w = t >> 5, lane = t & 31, g = lane >> 2, tig = lane & 3;
    const int wm = (w >> 1) * 32, wn = (w & 1) * 32;
    const int m0 = blockIdx.y * 128, n0 = blockIdx.x * 64;
    const int li = lane & 7, lj = lane >> 3;

    const unsigned ABUF = 128 * GAS * 4, BBUF = 64 * GAS * 4;
    const unsigned adrA0 = sptr(&As[0][wm + (lj & 1) * 8 + li][(lj >> 1) * 4]);
    const unsigned adrA1 = adrA0 + 16 * GAS * 4;
    const unsigned adrB  = sptr(&Bs[0][wn + lj * 8 + li][0]);

    const int ar = t >> 2, ac4 = t & 3;
    #define GEMM_LOAD(k0_, buf_) do {                                           \
        cpa16(sptr(&As[buf_][ar][ac4*4]),    &A[(size_t)(m0+ar)*K + (k0_) + ac4*8]); \
        cpa16(sptr(&As[buf_][ar+64][ac4*4]), &A[(size_t)(m0+ar+64)*K + (k0_) + ac4*8]); \
        cpa16(sptr(&Bs[buf_][ar][ac4*4]),    &Bt[(size_t)(n0+ar)*K + (k0_) + ac4*8]); \
    } while(0)

    GEMM_LOAD(0, 0);
    CP_COMMIT();

    float Co[2][4][4] = {};
    const int KT = K / 32;
    for (int kt = 0; kt < KT; kt++) {
        CP_WAIT0();
        __syncthreads();
        if (kt + 1 < KT) { GEMM_LOAD((kt + 1) * 32, (kt + 1) & 1); CP_COMMIT(); }
        const unsigned oa = (kt & 1) * ABUF, ob = (kt & 1) * BBUF;

        #pragma unroll
        for (int ks = 0; ks < 2; ks++) {
            unsigned cb = ks * 32;
            unsigned a0[4], a1[4], b0[4], b1[4];
            ldm4(a0, adrA0 + oa + cb);
            ldm4(a1, adrA1 + oa + cb);
            ldm4(b0, adrB + ob + cb);
            ldm4(b1, adrB + ob + cb + 16);
            #pragma unroll
            for (int nt = 0; nt < 4; nt++) {
                unsigned b[2] = { b0[nt], b1[nt] };
                mma16(Co[0][nt], a0, b);
                mma16(Co[1][nt], a1, b);
            }
        }
        __syncthreads();
    }

    #pragma unroll
    for (int mt = 0; mt < 2; mt++)
        #pragma unroll
        for (int nt = 0; nt < 4; nt++) {
            int r = m0 + wm + mt * 16 + g;
            int c = n0 + wn + nt * 8 + 2 * tig;
            *(float2*)&C[(size_t)r * N + c]       = make_float2(Co[mt][nt][0], Co[mt][nt][1]);
            *(float2*)&C[(size_t)(r + 8) * N + c] = make_float2(Co[mt][nt][2], Co[mt][nt][3]);
        }
}

// ---------------- fused attention: register-resident S ----------------
// grid (SEQ/128, BATCH*NH), 256 thr (8 warps), warp = 16 q-rows x full 64 keys.
#define AQS  12   // Qs/Ks u32 stride
#define AVSH 72   // Vs half stride
__global__ __launch_bounds__(256) void attn_f16(
    const __half* __restrict__ gq, const __half* __restrict__ gk,
    const __half* __restrict__ gv, __half* __restrict__ gao)
{
    __shared__ unsigned Qs[128][AQS];
    __shared__ unsigned Ks[2][64][AQS];
    __shared__ __half   Vs[2][64][AVSH];

    const int t = threadIdx.x;
    const int w = t >> 5, lane = t & 31, g = lane >> 2, tig = lane & 3;
    const int wm = w * 16;
    const int bh = blockIdx.y, q0 = blockIdx.x * 128;
    const int li = lane & 7, lj = lane >> 3;

    const __half* qb = gq + (size_t)bh * SEQ * DKH;
    const __half* kb = gk + (size_t)bh * SEQ * DKH;
    const __half* vb = gv + (size_t)bh * SEQ * DVH;

    // Q tile 128x16 (plain stores)
    {
        int r = t >> 1, hf = t & 1;
        *(uint4*)&Qs[r][hf * 4] = *(const uint4*)&qb[(size_t)(q0 + r) * DKH + hf * 8];
    }

    const int kr = t >> 1, khf = t & 1;          // K loader mapping (t<128)
    const int vr = t >> 3, vc = (t & 7) * 8;     // V loader mapping (x2)
    #define ATTN_LOAD(k0_, buf_) do {                                            \
        if (t < 128)                                                             \
            cpa16(sptr(&Ks[buf_][kr][khf*4]), &kb[(size_t)((k0_)+kr)*DKH + khf*8]); \
        cpa16(sptr(&Vs[buf_][vr][vc]),      &vb[(size_t)((k0_)+vr)*DVH + vc]);   \
        cpa16(sptr(&Vs[buf_][vr+32][vc]),   &vb[(size_t)((k0_)+vr+32)*DVH + vc]);\
    } while(0)

    ATTN_LOAD(0, 0);
    CP_COMMIT();
    __syncthreads();   // Qs visible

    unsigned aq[4];
    ldm4(aq, sptr(&Qs[wm + (lj & 1) * 8 + li][(lj >> 1) * 4]));

    const unsigned KBUF = 64 * AQS * 4, VBUF = 64 * AVSH * 2;
    const unsigned adrK = sptr(&Ks[0][lj * 8 + li][0]);
    const unsigned adrV = sptr(&Vs[0][(lj & 1) * 8 + li][(lj >> 1) * 8]);

    float Co[8][4] = {};

    const int NT = SEQ / 64;
    for (int kt = 0; kt < NT; kt++) {
        CP_WAIT0();
        __syncthreads();
        if (kt + 1 < NT) { ATTN_LOAD((kt + 1) * 64, (kt + 1) & 1); CP_COMMIT(); }
        const unsigned kbase = adrK + (kt & 1) * KBUF;
        const unsigned vbase = adrV + (kt & 1) * VBUF;

        // ---- S = Q @ K^T over 64 keys (8 n-tiles) ----
        float Cs[8][4] = {};
        {
            unsigned b0[4], b1[4], b2[4], b3[4];
            ldm4(b0, kbase);
            ldm4(b1, kbase + 16);
            ldm4(b2, kbase + 32 * AQS * 4);
            ldm4(b3, kbase + 32 * AQS * 4 + 16);
            #pragma unroll
            for (int nt = 0; nt < 4; nt++) {
                unsigned bA[2] = { b0[nt], b1[nt] };
                unsigned bB[2] = { b2[nt], b3[nt] };
                mma16(Cs[nt],     aq, bA);
                mma16(Cs[4 + nt], aq, bB);
            }
        }

        // relu^2 -> fp16 A-fragments (registers only; C layout == A layout)
        unsigned sf[4][4];
        #pragma unroll
        for (int ks = 0; ks < 4; ks++) {
            float r0 = Cs[2*ks][0];   r0 = r0 > 0.f ? r0*r0 : 0.f;
            float r1 = Cs[2*ks][1];   r1 = r1 > 0.f ? r1*r1 : 0.f;
            float r2 = Cs[2*ks][2];   r2 = r2 > 0.f ? r2*r2 : 0.f;
            float r3 = Cs[2*ks][3];   r3 = r3 > 0.f ? r3*r3 : 0.f;
            float r4 = Cs[2*ks+1][0]; r4 = r4 > 0.f ? r4*r4 : 0.f;
            float r5 = Cs[2*ks+1][1]; r5 = r5 > 0.f ? r5*r5 : 0.f;
            float r6 = Cs[2*ks+1][2]; r6 = r6 > 0.f ? r6*r6 : 0.f;
            float r7 = Cs[2*ks+1][3]; r7 = r7 > 0.f ? r7*r7 : 0.f;
            sf[ks][0] = packh2(r0, r1);
            sf[ks][1] = packh2(r2, r3);
            sf[ks][2] = packh2(r4, r5);
            sf[ks][3] = packh2(r6, r7);
        }

        // ---- Out += S @ V (4 k16 steps x 8 dv-tiles) ----
        #pragma unroll
        for (int ks = 0; ks < 4; ks++) {
            const unsigned vk = vbase + ks * 16 * AVSH * 2;
            #pragma unroll
            for (int j = 0; j < 4; j++) {
                unsigned vv[4];
                ldm4t(vv, vk + j * 32);
                unsigned bA[2] = { vv[0], vv[1] };
                unsigned bB[2] = { vv[2], vv[3] };
                mma16(Co[2*j],     sf[ks], bA);
                mma16(Co[2*j + 1], sf[ks], bB);
            }
        }
        __syncthreads();
    }

    // ---- epilogue: tanh-norm, registers + shuffle only ----
    float s0 = 0.f, s1 = 0.f;
    #pragma unroll
    for (int nt = 0; nt < 8; nt++) {
        s0 += Co[nt][0]*Co[nt][0] + Co[nt][1]*Co[nt][1];
        s1 += Co[nt][2]*Co[nt][2] + Co[nt][3]*Co[nt][3];
    }
    s0 += __shfl_xor_sync(~0u, s0, 1); s0 += __shfl_xor_sync(~0u, s0, 2);
    s1 += __shfl_xor_sync(~0u, s1, 1); s1 += __shfl_xor_sync(~0u, s1, 2);
    float n0s = sqrtf(s0), n1s = sqrtf(s1);
    float sc0 = tanhf(n0s) / fmaxf(n0s, 1e-12f);
    float sc1 = tanhf(n1s) / fmaxf(n1s, 1e-12f);

    const int b_ = bh >> 4, h_ = bh & 15;
    const int row0 = q0 + wm + g, row1 = row0 + 8;
    __half* d0 = gao + (size_t)(b_ * SEQ + row0) * OCOLS + h_ * DVH;
    __half* d1 = gao + (size_t)(b_ * SEQ + row1) * OCOLS + h_ * DVH;
    #pragma unroll
    for (int nt = 0; nt < 8; nt++) {
        int c = nt * 8 + 2 * tig;
        *(unsigned*)&d0[c] = packh2(Co[nt][0] * sc0, Co[nt][1] * sc0);
        *(unsigned*)&d1[c] = packh2(Co[nt][2] * sc1, Co[nt][3] * sc1);
    }
}

// ---------------- host launch ----------------
extern "C" void kernel_launch(void* const* d_in, const int* in_sizes, int n_in,
                              void* d_out, int out_size)
{
    const float *tokens = nullptr, *Wq = nullptr, *Wkv = nullptr, *Wout = nullptr;
    for (int i = 0; i < n_in; i++) {
        switch (in_sizes[i]) {
            case NTOK * DIM:   tokens = (const float*)d_in[i]; break;
            case DIM * QCOLS:  Wq     = (const float*)d_in[i]; break;
            case DIM * KVCOLS: Wkv    = (const float*)d_in[i]; break;
            case OCOLS * DIM:  Wout   = (const float*)d_in[i]; break;
        }
    }

    __half *tokh, *wc, *wot, *qn, *kn, *vh, *aoh;
    cudaGetSymbolAddress((void**)&tokh, g_tokh);
    cudaGetSymbolAddress((void**)&wc,   g_wc);
    cudaGetSymbolAddress((void**)&wot,  g_wot);
    cudaGetSymbolAddress((void**)&qn,   g_qn);
    cudaGetSymbolAddress((void**)&kn,   g_kn);
    cudaGetSymbolAddress((void**)&vh,   g_vh);
    cudaGetSymbolAddress((void**)&aoh,  g_aoh);

    cvt_f2h<<<(NTOK*DIM/8 + 255)/256, 256>>>(tokens, tokh, NTOK*DIM/8);
    wprep<<<dim3(PCOLS/32, DIM/32), 256>>>(Wq, Wkv, wc);
    wtrans<<<dim3(DIM/32, OCOLS/32), 256>>>(Wout, wot, DIM, OCOLS);

    proj_gemm<<<dim3(PCOLS/64, NTOK/128), 256>>>(tokh, wc, qn, kn, vh);

    attn_f16<<<dim3(SEQ/128, BATCH*NH), 256>>>(qn, kn, vh, aoh);

    gemm_f16<<<dim3(DIM/64, NTOK/128), 256>>>(aoh, wot, (float*)d_out, NTOK, DIM, OCOLS);
}